// round 7
// baseline (speedup 1.0000x reference)
#include <cuda_runtime.h>

#define S_DIM 100000
#define G_DIM 18000
#define H_DIM 256
#define E_DIM 600000
#define B_DIM 256

#define G4_DIM 4500            // G_DIM/4
#define KT     16              // k-tiles (16 k's each)
#define NB_BUILD 576           // 36 g-blocks * 16 k-tiles
#define NB_CZERO 98            // coef zero blocks (128 thr * 2 float4 = 256 f4 each)
#define FLAG_TARGET (NB_BUILD + NB_CZERO)   // 674
#define NB_SCAT  1172          // ceil(150000 quads / 128)
#define NB_C0    18            // const0 tail blocks (1000 genes each)
#define CHUNKS 50
#define ROWS   8

__device__ float g_v[G_DIM];
__device__ float g_coef[S_DIM];
__device__ float g_const0;
__device__ int   g_done;

// ---------------------------------------------------------------------------
// Kernel 1 (tiny): zero v, out, const0, done flag.
__global__ void k_prep(float* __restrict__ out) {
    int i = blockIdx.x * blockDim.x + threadIdx.x;   // 72*256 = 18432
    if (i < G_DIM) g_v[i] = 0.0f;
    if (i < B_DIM) out[i] = 0.0f;
    if (i == 0) { g_const0 = 0.0f; g_done = 0; }
}

// ---------------------------------------------------------------------------
// Kernel 2 (fused chain): build_v + coef-zero (producers, low bids) ->
// flag -> scatter + const0 (consumers). Consumers preload their edge data
// BEFORE spinning, overlapping their DRAM traffic with build_v's.
__global__ void __launch_bounds__(128)
k_chain(const float* __restrict__ W1, const float* __restrict__ W2,
        const int* __restrict__ snp, const int* __restrict__ gidx,
        const float* __restrict__ ew, const float* __restrict__ gene_bias,
        const float* __restrict__ b1, const float* __restrict__ b2) {
    const int bid = blockIdx.x;
    const int tid = threadIdx.x;

    if (bid < NB_BUILD) {
        // ---- producer: v partial over a 16-k tile ----
        __shared__ float w2s[16];
        const int gb = bid % 36;
        const int k0 = (bid / 36) * 16;
        if (tid < 16) w2s[tid] = W2[k0 + tid];
        __syncthreads();
        int g4 = gb * 128 + tid;
        if (g4 < G4_DIM) {
            const float4* __restrict__ W14 = reinterpret_cast<const float4*>(W1);
            float4 acc = make_float4(0.f, 0.f, 0.f, 0.f);
            #pragma unroll
            for (int k = 0; k < 16; k++) {
                float4 w = __ldg(&W14[(size_t)(k0 + k) * G4_DIM + g4]);
                float s = w2s[k];
                acc.x = fmaf(w.x, s, acc.x);
                acc.y = fmaf(w.y, s, acc.y);
                acc.z = fmaf(w.z, s, acc.z);
                acc.w = fmaf(w.w, s, acc.w);
            }
            float* vo = &g_v[g4 * 4];
            atomicAdd(vo + 0, acc.x);
            atomicAdd(vo + 1, acc.y);
            atomicAdd(vo + 2, acc.z);
            atomicAdd(vo + 3, acc.w);
        }
        __threadfence();
        __syncthreads();
        if (tid == 0) atomicAdd(&g_done, 1);
        return;
    }

    if (bid < FLAG_TARGET) {
        // ---- producer: zero coef ----
        float4* c4 = reinterpret_cast<float4*>(g_coef);
        float4 z = make_float4(0.f, 0.f, 0.f, 0.f);
        int i = (bid - NB_BUILD) * 256 + tid;
        if (i < S_DIM / 4) c4[i] = z;
        i += 128;
        if (i < S_DIM / 4) c4[i] = z;
        __threadfence();
        __syncthreads();
        if (tid == 0) atomicAdd(&g_done, 1);
        return;
    }

    if (bid < FLAG_TARGET + NB_SCAT) {
        // ---- consumer: scatter. Preload edge quads, THEN wait for flag. ----
        int i4 = (bid - FLAG_TARGET) * 128 + tid;
        int4 s4, g4;
        float4 w4;
        bool valid = (i4 < E_DIM / 4);
        if (valid) {
            s4 = __ldg(reinterpret_cast<const int4*>(snp) + i4);
            g4 = __ldg(reinterpret_cast<const int4*>(gidx) + i4);
            w4 = __ldg(reinterpret_cast<const float4*>(ew) + i4);
        }
        // spin until all producers done (lead thread spins, block waits)
        if (tid == 0) {
            while (*((volatile int*)&g_done) < FLAG_TARGET) __nanosleep(64);
        }
        __syncthreads();
        __threadfence();   // acquire: order v reads after flag
        if (valid) {
            float v0 = g_v[g4.x], v1 = g_v[g4.y], v2 = g_v[g4.z], v3 = g_v[g4.w];
            atomicAdd(&g_coef[s4.x], w4.x * v0);
            atomicAdd(&g_coef[s4.y], w4.y * v1);
            atomicAdd(&g_coef[s4.z], w4.z * v2);
            atomicAdd(&g_coef[s4.w], w4.w * v3);
        }
        return;
    }

    // ---- consumer: const0 tail (needs final v) ----
    {
        const int local = bid - FLAG_TARGET - NB_SCAT;     // 0..17
        if (tid == 0) {
            while (*((volatile int*)&g_done) < FLAG_TARGET) __nanosleep(64);
        }
        __syncthreads();
        __threadfence();
        const int start = local * (G_DIM / NB_C0);         // 1000 per block
        float acc = 0.0f;
        for (int g = start + tid; g < start + G_DIM / NB_C0; g += 128)
            acc = fmaf(g_v[g], gene_bias[g], acc);
        if (local == 0) {
            acc = fmaf(W2[tid], b1[tid], acc);
            acc = fmaf(W2[tid + 128], b1[tid + 128], acc);
            if (tid == 0) acc += b2[0];
        }
        __shared__ float sm[4];
        int lane = tid & 31, wid = tid >> 5;
        #pragma unroll
        for (int o = 16; o > 0; o >>= 1) acc += __shfl_down_sync(0xffffffffu, acc, o);
        if (lane == 0) sm[wid] = acc;
        __syncthreads();
        if (tid == 0)
            atomicAdd(&g_const0, sm[0] + sm[1] + sm[2] + sm[3]);
    }
}

// ---------------------------------------------------------------------------
// Kernel 3: GEMV (proven config, at the measured ~5.2 TB/s ceiling).
// grid=(CHUNKS, B/ROWS)=(50,32)=1600.
__global__ void __launch_bounds__(256, 6)
k_gemv(const float* __restrict__ x, float* __restrict__ out) {
    const int per  = (S_DIM / 4) / CHUNKS;         // 500
    const int base = blockIdx.x * per;
    const int r0   = blockIdx.y * ROWS;
    const float4* __restrict__ cf = reinterpret_cast<const float4*>(g_coef);

    float acc[ROWS];
    #pragma unroll
    for (int j = 0; j < ROWS; j++) acc[j] = 0.0f;

    #pragma unroll
    for (int it = 0; it < 2; it++) {
        int off = it * 256 + threadIdx.x;
        if (off < per) {
            int i = base + off;
            float4 cv = __ldg(&cf[i]);
            #pragma unroll
            for (int j = 0; j < ROWS; j++) {
                float4 xv = __ldcs(reinterpret_cast<const float4*>(
                                x + (size_t)(r0 + j) * S_DIM) + i);
                acc[j] += xv.x * cv.x + xv.y * cv.y + xv.z * cv.z + xv.w * cv.w;
            }
        }
    }

    __shared__ float sm[ROWS][8];
    int lane = threadIdx.x & 31, wid = threadIdx.x >> 5;
    #pragma unroll
    for (int j = 0; j < ROWS; j++) {
        float v = acc[j];
        #pragma unroll
        for (int o = 16; o > 0; o >>= 1) v += __shfl_down_sync(0xffffffffu, v, o);
        if (lane == 0) sm[j][wid] = v;
    }
    __syncthreads();
    if (threadIdx.x < ROWS * 8) {
        int j = threadIdx.x >> 3, w = threadIdx.x & 7;
        float v = sm[j][w];
        #pragma unroll
        for (int o = 4; o > 0; o >>= 1) v += __shfl_down_sync(0xffffffffu, v, o);
        if (w == 0) {
            if (blockIdx.x == 0) v += g_const0;
            atomicAdd(&out[r0 + j], v);
        }
    }
}

// ---------------------------------------------------------------------------
extern "C" void kernel_launch(void* const* d_in, const int* in_sizes, int n_in,
                              void* d_out, int out_size) {
    const float* x    = (const float*)d_in[0];
    const int*   snp  = (const int*)  d_in[1];
    const int*   gidx = (const int*)  d_in[2];
    const float* ew   = (const float*)d_in[3];
    const float* gb   = (const float*)d_in[4];
    const float* W1   = (const float*)d_in[5];
    const float* b1   = (const float*)d_in[6];
    const float* W2   = (const float*)d_in[7];
    const float* b2   = (const float*)d_in[8];
    float* out = (float*)d_out;

    k_prep<<<72, 256>>>(out);
    k_chain<<<FLAG_TARGET + NB_SCAT + NB_C0, 128>>>(W1, W2, snp, gidx, ew, gb, b1, b2);
    k_gemv<<<dim3(CHUNKS, B_DIM / ROWS), 256>>>(x, out);
}

// round 8
// speedup vs baseline: 1.2602x; 1.2602x over previous
#include <cuda_runtime.h>

#define S_DIM 100000
#define G_DIM 18000
#define H_DIM 256
#define E_DIM 600000
#define B_DIM 256

#define KT      16     // k-tiles in build_v (16 k's each)
#define G4_DIM  4500   // G_DIM/4 float4 columns
#define CHUNKS  50     // gemv chunks along S (25000/50 = 500 float4 each)
#define ROWS    8      // gemv rows per block
#define SCAT_BLOCKS 586   // ceil(150000/256)
#define C0_BLOCKS   9     // const0 tail blocks (2000 g's each)

// INVARIANT: g_v == 0 and g_const0's staging starts fresh at every
// kernel_launch entry. Statically zero at module load; k_gemv re-zeroes
// g_v on exit (v is dead by then), k_build_v zeroes coef/out/const0 for
// the current call before their writers run.
__device__ float g_v[G_DIM];
__device__ float g_coef[S_DIM];
__device__ float g_const0;

// ---------------------------------------------------------------------------
// Kernel 1: grid=(36, KT+1), block=128.
//   y <  KT : v[4g..4g+3] += sum over 16-k tile of W1[k,*]*W2[k]
//             (g_v is zero at entry: static init / zeroed by previous gemv)
//   y == KT : zero coef + out + const0 (all precede their writers in order)
__global__ void __launch_bounds__(128)
k_build_v(const float* __restrict__ W1, const float* __restrict__ W2,
          float* __restrict__ out) {
    if (blockIdx.y == KT) {
        float4 z = make_float4(0.f, 0.f, 0.f, 0.f);
        float4* c4 = reinterpret_cast<float4*>(g_coef);
        for (int i = blockIdx.x * blockDim.x + threadIdx.x; i < S_DIM / 4; i += 36 * 128)
            c4[i] = z;
        if (blockIdx.x == 0) {
            out[threadIdx.x] = 0.0f;
            out[threadIdx.x + 128] = 0.0f;
            if (threadIdx.x == 0) g_const0 = 0.0f;
        }
        return;
    }
    __shared__ float w2s[16];
    const int k0 = blockIdx.y * 16;
    if (threadIdx.x < 16) w2s[threadIdx.x] = W2[k0 + threadIdx.x];
    __syncthreads();
    int g4 = blockIdx.x * blockDim.x + threadIdx.x;   // 0..4607
    if (g4 >= G4_DIM) return;
    const float4* __restrict__ W14 = reinterpret_cast<const float4*>(W1);
    float4 acc = make_float4(0.f, 0.f, 0.f, 0.f);
    #pragma unroll
    for (int k = 0; k < 16; k++) {
        float4 w = __ldg(&W14[(size_t)(k0 + k) * G4_DIM + g4]);
        float s = w2s[k];
        acc.x = fmaf(w.x, s, acc.x);
        acc.y = fmaf(w.y, s, acc.y);
        acc.z = fmaf(w.z, s, acc.z);
        acc.w = fmaf(w.w, s, acc.w);
    }
    float* vo = &g_v[g4 * 4];
    atomicAdd(vo + 0, acc.x);
    atomicAdd(vo + 1, acc.y);
    atomicAdd(vo + 2, acc.z);
    atomicAdd(vo + 3, acc.w);
}

// ---------------------------------------------------------------------------
// Kernel 2: edge scatter (4 edges/thread, vectorized) + const0 tail blocks.
__global__ void k_scatter(const int* __restrict__ snp, const int* __restrict__ gidx,
                          const float* __restrict__ ew,
                          const float* __restrict__ gene_bias,
                          const float* __restrict__ b1, const float* __restrict__ W2,
                          const float* __restrict__ b2) {
    if (blockIdx.x < SCAT_BLOCKS) {
        int i4 = blockIdx.x * blockDim.x + threadIdx.x;     // quad index
        if (i4 >= E_DIM / 4) return;
        int4   s4 = reinterpret_cast<const int4*>(snp)[i4];
        int4   g4 = reinterpret_cast<const int4*>(gidx)[i4];
        float4 w4 = reinterpret_cast<const float4*>(ew)[i4];
        float v0 = g_v[g4.x], v1 = g_v[g4.y], v2 = g_v[g4.z], v3 = g_v[g4.w];
        atomicAdd(&g_coef[s4.x], w4.x * v0);
        atomicAdd(&g_coef[s4.y], w4.y * v1);
        atomicAdd(&g_coef[s4.z], w4.z * v2);
        atomicAdd(&g_coef[s4.w], w4.w * v3);
        return;
    }
    // ---- const0 tail ----
    int local = blockIdx.x - SCAT_BLOCKS;                   // 0..8
    int start = local * (G_DIM / C0_BLOCKS);                // 2000 per block
    float acc = 0.0f;
    for (int g = start + threadIdx.x; g < start + G_DIM / C0_BLOCKS; g += blockDim.x)
        acc = fmaf(g_v[g], gene_bias[g], acc);
    if (local == 0) {
        acc = fmaf(W2[threadIdx.x], b1[threadIdx.x], acc);  // blockDim == H_DIM
        if (threadIdx.x == 0) acc += b2[0];
    }
    __shared__ float sm[32];
    int lane = threadIdx.x & 31, wid = threadIdx.x >> 5;
    #pragma unroll
    for (int o = 16; o > 0; o >>= 1) acc += __shfl_down_sync(0xffffffffu, acc, o);
    if (lane == 0) sm[wid] = acc;
    __syncthreads();
    if (wid == 0) {
        acc = (lane < (blockDim.x >> 5)) ? sm[lane] : 0.0f;
        #pragma unroll
        for (int o = 16; o > 0; o >>= 1) acc += __shfl_down_sync(0xffffffffu, acc, o);
        if (lane == 0) atomicAdd(&g_const0, acc);
    }
}

// ---------------------------------------------------------------------------
// Kernel 3: GEMV (proven config, ~5.2 TB/s measured ceiling for this pattern).
// grid=(CHUNKS, B/ROWS)=(50,32)=1600. Epilogue: blockIdx.x==0 blocks re-zero
// g_v (dead here) to restore the entry invariant for the next launch.
__global__ void __launch_bounds__(256, 6)
k_gemv(const float* __restrict__ x, float* __restrict__ out) {
    const int per  = (S_DIM / 4) / CHUNKS;         // 500
    const int base = blockIdx.x * per;
    const int r0   = blockIdx.y * ROWS;
    const float4* __restrict__ cf = reinterpret_cast<const float4*>(g_coef);

    float acc[ROWS];
    #pragma unroll
    for (int j = 0; j < ROWS; j++) acc[j] = 0.0f;

    #pragma unroll
    for (int it = 0; it < 2; it++) {
        int off = it * 256 + threadIdx.x;
        if (off < per) {
            int i = base + off;
            float4 cv = __ldg(&cf[i]);
            #pragma unroll
            for (int j = 0; j < ROWS; j++) {
                float4 xv = __ldcs(reinterpret_cast<const float4*>(
                                x + (size_t)(r0 + j) * S_DIM) + i);
                acc[j] += xv.x * cv.x + xv.y * cv.y + xv.z * cv.z + xv.w * cv.w;
            }
        }
    }

    __shared__ float sm[ROWS][8];
    int lane = threadIdx.x & 31, wid = threadIdx.x >> 5;
    #pragma unroll
    for (int j = 0; j < ROWS; j++) {
        float v = acc[j];
        #pragma unroll
        for (int o = 16; o > 0; o >>= 1) v += __shfl_down_sync(0xffffffffu, v, o);
        if (lane == 0) sm[j][wid] = v;
    }
    __syncthreads();
    if (threadIdx.x < ROWS * 8) {
        int j = threadIdx.x >> 3, w = threadIdx.x & 7;
        float v = sm[j][w];
        #pragma unroll
        for (int o = 4; o > 0; o >>= 1) v += __shfl_down_sync(0xffffffffu, v, o);
        if (w == 0) {
            if (blockIdx.x == 0) v += g_const0;    // exactly one chunk adds const0
            atomicAdd(&out[r0 + j], v);
        }
    }

    // ---- epilogue: restore g_v == 0 for the next kernel_launch call ----
    if (blockIdx.x == 0) {
        int i = blockIdx.y * 256 + threadIdx.x;    // 8192 threads over 18000
        #pragma unroll
        for (int rep = 0; rep < 3; rep++, i += 8192)
            if (i < G_DIM) g_v[i] = 0.0f;
    }
}

// ---------------------------------------------------------------------------
extern "C" void kernel_launch(void* const* d_in, const int* in_sizes, int n_in,
                              void* d_out, int out_size) {
    const float* x    = (const float*)d_in[0];
    const int*   snp  = (const int*)  d_in[1];
    const int*   gidx = (const int*)  d_in[2];
    const float* ew   = (const float*)d_in[3];
    const float* gb   = (const float*)d_in[4];
    const float* W1   = (const float*)d_in[5];
    const float* b1   = (const float*)d_in[6];
    const float* W2   = (const float*)d_in[7];
    const float* b2   = (const float*)d_in[8];
    float* out = (float*)d_out;

    k_build_v<<<dim3(36, KT + 1), 128>>>(W1, W2, out);
    k_scatter<<<SCAT_BLOCKS + C0_BLOCKS, 256>>>(snp, gidx, ew, gb, b1, W2, b2);
    k_gemv<<<dim3(CHUNKS, B_DIM / ROWS), 256>>>(x, out);
}

// round 9
// speedup vs baseline: 1.2705x; 1.0082x over previous
#include <cuda_runtime.h>

#define S_DIM 100000
#define G_DIM 18000
#define H_DIM 256
#define E_DIM 600000
#define B_DIM 256

#define KT      32     // k-tiles in build_v
#define KS      8      // k's per tile (KT*KS = H_DIM)
#define G4_DIM  4500   // G_DIM/4 float4 columns
#define CHUNKS  50     // gemv chunks along S (25000/50 = 500 float4 each)
#define ROWS    8      // gemv rows per block
#define SCAT_BLOCKS 586   // ceil(150000/256)
#define C0_BLOCKS   9     // const0 tail blocks (2000 g's each)

// INVARIANT: g_v == 0 at every kernel_launch entry (statically zero at load;
// k_gemv re-zeroes it on exit, when v is dead). k_build_v's extra grid.y
// slice zeroes coef/out/const0 before their writers run.
__device__ float g_v[G_DIM];
__device__ float g_coef[S_DIM];
__device__ float g_const0;

// ---------------------------------------------------------------------------
// Kernel 1: grid=(36, KT+1), block=128.
//   y <  KT : v[4g..4g+3] += sum over 8-k tile of W1[k,*]*W2[k]
//             Loads explicitly batched (8 independent LDG.128 in flight).
//   y == KT : zero coef + out + const0
__global__ void __launch_bounds__(128)
k_build_v(const float* __restrict__ W1, const float* __restrict__ W2,
          float* __restrict__ out) {
    if (blockIdx.y == KT) {
        float4 z = make_float4(0.f, 0.f, 0.f, 0.f);
        float4* c4 = reinterpret_cast<float4*>(g_coef);
        for (int i = blockIdx.x * blockDim.x + threadIdx.x; i < S_DIM / 4; i += 36 * 128)
            c4[i] = z;
        if (blockIdx.x == 0) {
            out[threadIdx.x] = 0.0f;
            out[threadIdx.x + 128] = 0.0f;
            if (threadIdx.x == 0) g_const0 = 0.0f;
        }
        return;
    }
    __shared__ float w2s[KS];
    const int k0 = blockIdx.y * KS;
    if (threadIdx.x < KS) w2s[threadIdx.x] = W2[k0 + threadIdx.x];
    __syncthreads();
    int g4 = blockIdx.x * blockDim.x + threadIdx.x;   // 0..4607
    if (g4 >= G4_DIM) return;
    const float4* __restrict__ W14 = reinterpret_cast<const float4*>(W1);

    // Phase 1: 8 independent loads (front-batched -> MLP=8)
    float4 w[KS];
    #pragma unroll
    for (int k = 0; k < KS; k++)
        w[k] = __ldg(&W14[(size_t)(k0 + k) * G4_DIM + g4]);

    // Phase 2: FMAs
    float4 acc = make_float4(0.f, 0.f, 0.f, 0.f);
    #pragma unroll
    for (int k = 0; k < KS; k++) {
        float s = w2s[k];
        acc.x = fmaf(w[k].x, s, acc.x);
        acc.y = fmaf(w[k].y, s, acc.y);
        acc.z = fmaf(w[k].z, s, acc.z);
        acc.w = fmaf(w[k].w, s, acc.w);
    }
    float* vo = &g_v[g4 * 4];
    atomicAdd(vo + 0, acc.x);
    atomicAdd(vo + 1, acc.y);
    atomicAdd(vo + 2, acc.z);
    atomicAdd(vo + 3, acc.w);
}

// ---------------------------------------------------------------------------
// Kernel 2: edge scatter (4 edges/thread, vectorized) + const0 tail blocks.
__global__ void k_scatter(const int* __restrict__ snp, const int* __restrict__ gidx,
                          const float* __restrict__ ew,
                          const float* __restrict__ gene_bias,
                          const float* __restrict__ b1, const float* __restrict__ W2,
                          const float* __restrict__ b2) {
    if (blockIdx.x < SCAT_BLOCKS) {
        int i4 = blockIdx.x * blockDim.x + threadIdx.x;     // quad index
        if (i4 >= E_DIM / 4) return;
        int4   s4 = reinterpret_cast<const int4*>(snp)[i4];
        int4   g4 = reinterpret_cast<const int4*>(gidx)[i4];
        float4 w4 = reinterpret_cast<const float4*>(ew)[i4];
        float v0 = g_v[g4.x], v1 = g_v[g4.y], v2 = g_v[g4.z], v3 = g_v[g4.w];
        atomicAdd(&g_coef[s4.x], w4.x * v0);
        atomicAdd(&g_coef[s4.y], w4.y * v1);
        atomicAdd(&g_coef[s4.z], w4.z * v2);
        atomicAdd(&g_coef[s4.w], w4.w * v3);
        return;
    }
    // ---- const0 tail ----
    int local = blockIdx.x - SCAT_BLOCKS;                   // 0..8
    int start = local * (G_DIM / C0_BLOCKS);                // 2000 per block
    float acc = 0.0f;
    for (int g = start + threadIdx.x; g < start + G_DIM / C0_BLOCKS; g += blockDim.x)
        acc = fmaf(g_v[g], gene_bias[g], acc);
    if (local == 0) {
        acc = fmaf(W2[threadIdx.x], b1[threadIdx.x], acc);  // blockDim == H_DIM
        if (threadIdx.x == 0) acc += b2[0];
    }
    __shared__ float sm[32];
    int lane = threadIdx.x & 31, wid = threadIdx.x >> 5;
    #pragma unroll
    for (int o = 16; o > 0; o >>= 1) acc += __shfl_down_sync(0xffffffffu, acc, o);
    if (lane == 0) sm[wid] = acc;
    __syncthreads();
    if (wid == 0) {
        acc = (lane < (blockDim.x >> 5)) ? sm[lane] : 0.0f;
        #pragma unroll
        for (int o = 16; o > 0; o >>= 1) acc += __shfl_down_sync(0xffffffffu, acc, o);
        if (lane == 0) atomicAdd(&g_const0, acc);
    }
}

// ---------------------------------------------------------------------------
// Kernel 3: GEMV (proven config, ~5.2 TB/s measured ceiling for this pattern).
// grid=(CHUNKS, B/ROWS)=(50,32)=1600. Epilogue: blockIdx.x==0 blocks re-zero
// g_v (dead here) to restore the entry invariant for the next launch.
__global__ void __launch_bounds__(256, 6)
k_gemv(const float* __restrict__ x, float* __restrict__ out) {
    const int per  = (S_DIM / 4) / CHUNKS;         // 500
    const int base = blockIdx.x * per;
    const int r0   = blockIdx.y * ROWS;
    const float4* __restrict__ cf = reinterpret_cast<const float4*>(g_coef);

    float acc[ROWS];
    #pragma unroll
    for (int j = 0; j < ROWS; j++) acc[j] = 0.0f;

    #pragma unroll
    for (int it = 0; it < 2; it++) {
        int off = it * 256 + threadIdx.x;
        if (off < per) {
            int i = base + off;
            float4 cv = __ldg(&cf[i]);
            #pragma unroll
            for (int j = 0; j < ROWS; j++) {
                float4 xv = __ldcs(reinterpret_cast<const float4*>(
                                x + (size_t)(r0 + j) * S_DIM) + i);
                acc[j] += xv.x * cv.x + xv.y * cv.y + xv.z * cv.z + xv.w * cv.w;
            }
        }
    }

    __shared__ float sm[ROWS][8];
    int lane = threadIdx.x & 31, wid = threadIdx.x >> 5;
    #pragma unroll
    for (int j = 0; j < ROWS; j++) {
        float v = acc[j];
        #pragma unroll
        for (int o = 16; o > 0; o >>= 1) v += __shfl_down_sync(0xffffffffu, v, o);
        if (lane == 0) sm[j][wid] = v;
    }
    __syncthreads();
    if (threadIdx.x < ROWS * 8) {
        int j = threadIdx.x >> 3, w = threadIdx.x & 7;
        float v = sm[j][w];
        #pragma unroll
        for (int o = 4; o > 0; o >>= 1) v += __shfl_down_sync(0xffffffffu, v, o);
        if (w == 0) {
            if (blockIdx.x == 0) v += g_const0;    // exactly one chunk adds const0
            atomicAdd(&out[r0 + j], v);
        }
    }

    // ---- epilogue: restore g_v == 0 for the next kernel_launch call ----
    if (blockIdx.x == 0) {
        int i = blockIdx.y * 256 + threadIdx.x;    // 8192 threads over 18000
        #pragma unroll
        for (int rep = 0; rep < 3; rep++, i += 8192)
            if (i < G_DIM) g_v[i] = 0.0f;
    }
}

// ---------------------------------------------------------------------------
extern "C" void kernel_launch(void* const* d_in, const int* in_sizes, int n_in,
                              void* d_out, int out_size) {
    const float* x    = (const float*)d_in[0];
    const int*   snp  = (const int*)  d_in[1];
    const int*   gidx = (const int*)  d_in[2];
    const float* ew   = (const float*)d_in[3];
    const float* gb   = (const float*)d_in[4];
    const float* W1   = (const float*)d_in[5];
    const float* b1   = (const float*)d_in[6];
    const float* W2   = (const float*)d_in[7];
    const float* b2   = (const float*)d_in[8];
    float* out = (float*)d_out;

    k_build_v<<<dim3(36, KT + 1), 128>>>(W1, W2, out);
    k_scatter<<<SCAT_BLOCKS + C0_BLOCKS, 256>>>(snp, gidx, ew, gb, b1, W2, b2);
    k_gemv<<<dim3(CHUNKS, B_DIM / ROWS), 256>>>(x, out);
}